// round 3
// baseline (speedup 1.0000x reference)
#include <cuda_runtime.h>
#include <math.h>

// ---------------- problem constants ----------------
#define BATCH 4
#define TLEN  131072          // waveform length
#define T1    32768           // after conv1 (stride 4)
#define T2    8192            // after conv2 (stride 4)
#define DCH   128             // channels / code dim
#define KCODE 2048            // codebook size
#define NROWS (BATCH*T2)      // 32768 VQ rows

#define XR_OFF  3
#define IDX_OFF (3 + BATCH*TLEN)   // 3 + 524288

// ---------------- scratch (device globals; no cudaMalloc allowed) ----------------
// NOTE: never pass these as kernel arguments from host code (host shadow symbol
// trap on ATS systems) — always reference them directly from device code.
__device__ float g_buf1[BATCH*DCH*T1];   // z1, later reused as decoder upsample-1 output
__device__ float g_z2 [BATCH*DCH*T2];
__device__ float g_z  [BATCH*DCH*T2];    // raw z, d-major (for commitment loss)
__device__ float g_znt[NROWS*DCH];       // normalized z, t-major [row][d]
__device__ float g_zq [BATCH*DCH*T2];
__device__ float g_h  [BATCH*DCH*T2];
__device__ float g_embnT[DCH*KCODE];     // normalized embedding, TRANSPOSED [d][e]
__device__ int   g_idx[NROWS];
__device__ double g_acc[2];              // [0]=rec sum, [1]=com sum

__device__ __forceinline__ float gelu_exact(float v) {
    return 0.5f * v * (1.0f + erff(v * 0.70710678118654752440f));
}

// ---------------- zero accumulators ----------------
__global__ void k_zero() {
    if (threadIdx.x < 2) g_acc[threadIdx.x] = 0.0;
}

// ---------------- conv1: [B,1,T] -> gelu -> [B,128,T1], k=8, s=4, p=2 ----------------
__global__ void k_conv1(const float* __restrict__ x, const float* __restrict__ w,
                        const float* __restrict__ bias) {
    __shared__ float sx[1032];
    __shared__ float sw[1024];
    __shared__ float sb[128];
    const int b  = blockIdx.y;
    const int t0 = blockIdx.x * 256;
    const int in0 = 4 * t0 - 2;
    for (int i = threadIdx.x; i < 1032; i += 256) {
        int p = in0 + i;
        sx[i] = (p >= 0 && p < TLEN) ? x[b * TLEN + p] : 0.f;
    }
    for (int i = threadIdx.x; i < 1024; i += 256) sw[i] = w[i];
    if (threadIdx.x < 128) sb[threadIdx.x] = bias[threadIdx.x];
    __syncthreads();
    const int t = threadIdx.x;
    for (int c = 0; c < 128; ++c) {
        float a = sb[c];
        #pragma unroll
        for (int j = 0; j < 8; ++j) a += sw[c * 8 + j] * sx[4 * t + j];
        g_buf1[((size_t)(b * DCH + c)) * T1 + t0 + t] = gelu_exact(a);
    }
}

// ---------------- conv2: [B,128,T1] -> gelu -> [B,128,T2], k=8, s=4, p=2 ----------------
__global__ void k_conv2(const float* __restrict__ w, const float* __restrict__ bias) {
    __shared__ float s[128 * 68];
    const int b  = blockIdx.y;
    const int t0 = blockIdx.x * 16;
    const int in0 = 4 * t0 - 2;
    for (int i = threadIdx.x; i < 128 * 68; i += 128) {
        int ci = i / 68, li = i % 68;
        int p = in0 + li;
        s[i] = (p >= 0 && p < T1) ? g_buf1[((size_t)(b * DCH + ci)) * T1 + p] : 0.f;
    }
    __syncthreads();
    const int c = threadIdx.x;
    float acc[16];
    {
        float bv = bias[c];
        #pragma unroll
        for (int t = 0; t < 16; ++t) acc[t] = bv;
    }
    for (int ci = 0; ci < 128; ++ci) {
        const float* wp = w + (c * 128 + ci) * 8;
        const float4 wa = *(const float4*)wp;
        const float4 wb = *(const float4*)(wp + 4);
        const float4* row = (const float4*)(s + ci * 68);
        float4 v = row[0];
        #pragma unroll
        for (int t = 0; t < 16; ++t) {
            float4 vn = row[t + 1];
            acc[t] += wa.x * v.x + wa.y * v.y + wa.z * v.z + wa.w * v.w
                    + wb.x * vn.x + wb.y * vn.y + wb.z * vn.z + wb.w * vn.w;
            v = vn;
        }
    }
    float* outp = g_z2 + ((size_t)(b * DCH + c)) * T2 + t0;
    #pragma unroll
    for (int t = 0; t < 16; ++t) outp[t] = gelu_exact(acc[t]);
}

// ---------------- k3 conv (s=1, p=1) ----------------
// STAGE 0: enc conv3, g_z2 -> g_z (raw, d-major) + g_znt (L2-normalized, t-major)
// STAGE 1: dec conv0, g_zq -> gelu -> g_h
template <int STAGE>
__global__ void k_conv3(const float* __restrict__ w, const float* __restrict__ bias) {
    const float* __restrict__ in = (STAGE == 0) ? g_z2 : g_zq;
    __shared__ float s[128 * 36];    // span 34, padded; reused for norm reduction (needs 32*132=4224 <= 4608)
    __shared__ float sinv[32];
    const int b  = blockIdx.y;
    const int t0 = blockIdx.x * 32;
    const int in0 = t0 - 1;
    for (int i = threadIdx.x; i < 128 * 34; i += 128) {
        int ci = i / 34, li = i % 34;
        int p = in0 + li;
        s[ci * 36 + li] = (p >= 0 && p < T2) ? in[((size_t)(b * DCH + ci)) * T2 + p] : 0.f;
    }
    __syncthreads();
    const int c = threadIdx.x;
    float acc[32];
    {
        float bv = bias[c];
        #pragma unroll
        for (int t = 0; t < 32; ++t) acc[t] = bv;
    }
    for (int ci = 0; ci < 128; ++ci) {
        const float* wp = w + (c * 128 + ci) * 3;
        float w0 = wp[0], w1 = wp[1], w2 = wp[2];
        const float* row = s + ci * 36;
        float a = row[0], bb = row[1];
        #pragma unroll
        for (int t = 0; t < 32; ++t) {
            float cc = row[t + 2];
            acc[t] += w0 * a + w1 * bb + w2 * cc;
            a = bb; bb = cc;
        }
    }
    if (STAGE == 1) {
        float* outp = g_h + ((size_t)(b * DCH + c)) * T2 + t0;
        #pragma unroll
        for (int t = 0; t < 32; ++t) outp[t] = gelu_exact(acc[t]);
        return;
    }
    // STAGE 0: fused row normalization across channels (block owns all 128 c)
    __syncthreads();   // done reading conv input from s
    #pragma unroll
    for (int t = 0; t < 32; ++t) s[t * 132 + c] = acc[t] * acc[t];
    __syncthreads();
    {
        const int t = threadIdx.x >> 2;
        const int q = threadIdx.x & 3;
        float sm = 0.f;
        #pragma unroll
        for (int j = 0; j < 32; ++j) sm += s[t * 132 + q * 32 + j];
        sm += __shfl_xor_sync(0xffffffffu, sm, 1);
        sm += __shfl_xor_sync(0xffffffffu, sm, 2);
        if (q == 0) sinv[t] = 1.0f / fmaxf(sqrtf(sm), 1e-12f);
    }
    __syncthreads();
    {
        float* outp = g_z + ((size_t)(b * DCH + c)) * T2 + t0;
        #pragma unroll
        for (int t = 0; t < 32; ++t) {
            outp[t] = acc[t];
            g_znt[(size_t)(b * T2 + t0 + t) * DCH + c] = acc[t] * sinv[t];
        }
    }
}

// ---------------- normalize embedding rows, store transposed [d][e] ----------------
__global__ void k_embnorm(const float* __restrict__ emb) {
    const int e    = blockIdx.x * 8 + (threadIdx.x >> 5);
    const int lane = threadIdx.x & 31;
    float4 v = *(const float4*)(emb + (size_t)e * DCH + lane * 4);
    float ss = v.x * v.x + v.y * v.y + v.z * v.z + v.w * v.w;
    #pragma unroll
    for (int o = 16; o > 0; o >>= 1) ss += __shfl_xor_sync(0xffffffffu, ss, o);
    float inv = 1.0f / fmaxf(sqrtf(ss), 1e-12f);
    g_embnT[(size_t)(lane * 4 + 0) * KCODE + e] = v.x * inv;
    g_embnT[(size_t)(lane * 4 + 1) * KCODE + e] = v.y * inv;
    g_embnT[(size_t)(lane * 4 + 2) * KCODE + e] = v.z * inv;
    g_embnT[(size_t)(lane * 4 + 3) * KCODE + e] = v.w * inv;
}

// ---------------- VQ GEMM + argmax: [64 rows] x [2048 codes] per block ----------------
// A = g_znt (row-major [row][k]), B = g_embnT (row-major [k][e]). 256 threads.
// Thread tile 4x4 over a 64x64 col tile; 32 col tiles; k split in two 64-halves.
__global__ void k_vqgemm() {
    __shared__ float sA[64 * 128];   // [row][k]   32KB
    __shared__ float sB[64 * 64];    // [k'][c]    16KB
    const int row0 = blockIdx.x * 64;
    for (int it = threadIdx.x; it < 64 * 32; it += 256) {
        int kq = it & 31, row = it >> 5;
        *(float4*)&sA[row * 128 + kq * 4] =
            *(const float4*)&g_znt[(size_t)(row0 + row) * DCH + kq * 4];
    }
    const int tr = threadIdx.x >> 4;    // 0..15 (4 rows each)
    const int tc = threadIdx.x & 15;    // 0..15 (4 cols each)
    float best[4] = {-1e30f, -1e30f, -1e30f, -1e30f};
    int   bidx[4] = {0, 0, 0, 0};

    for (int ct = 0; ct < KCODE / 64; ++ct) {
        float acc[4][4];
        #pragma unroll
        for (int i = 0; i < 4; ++i)
            #pragma unroll
            for (int j = 0; j < 4; ++j) acc[i][j] = 0.f;
        #pragma unroll
        for (int kh = 0; kh < 2; ++kh) {
            __syncthreads();
            for (int it = threadIdx.x; it < 64 * 16; it += 256) {
                int c4 = it & 15, kk = it >> 4;
                *(float4*)&sB[kk * 64 + c4 * 4] =
                    *(const float4*)&g_embnT[(size_t)(kh * 64 + kk) * KCODE + ct * 64 + c4 * 4];
            }
            __syncthreads();
            #pragma unroll 4
            for (int k = 0; k < 64; ++k) {
                float4 bv = *(const float4*)&sB[k * 64 + tc * 4];
                float a0 = sA[(tr * 4 + 0) * 128 + kh * 64 + k];
                float a1 = sA[(tr * 4 + 1) * 128 + kh * 64 + k];
                float a2 = sA[(tr * 4 + 2) * 128 + kh * 64 + k];
                float a3 = sA[(tr * 4 + 3) * 128 + kh * 64 + k];
                acc[0][0] += a0 * bv.x; acc[0][1] += a0 * bv.y; acc[0][2] += a0 * bv.z; acc[0][3] += a0 * bv.w;
                acc[1][0] += a1 * bv.x; acc[1][1] += a1 * bv.y; acc[1][2] += a1 * bv.z; acc[1][3] += a1 * bv.w;
                acc[2][0] += a2 * bv.x; acc[2][1] += a2 * bv.y; acc[2][2] += a2 * bv.z; acc[2][3] += a2 * bv.w;
                acc[3][0] += a3 * bv.x; acc[3][1] += a3 * bv.y; acc[3][2] += a3 * bv.z; acc[3][3] += a3 * bv.w;
            }
        }
        const int cbase = ct * 64 + tc * 4;
        #pragma unroll
        for (int i = 0; i < 4; ++i)
            #pragma unroll
            for (int j = 0; j < 4; ++j)
                if (acc[i][j] > best[i]) { best[i] = acc[i][j]; bidx[i] = cbase + j; }
    }
    // reduce across the 16 col-threads (half-warp groups; first-max tie break)
    #pragma unroll
    for (int o = 1; o < 16; o <<= 1) {
        #pragma unroll
        for (int i = 0; i < 4; ++i) {
            float ov = __shfl_xor_sync(0xffffffffu, best[i], o);
            int   oi = __shfl_xor_sync(0xffffffffu, bidx[i], o);
            if (ov > best[i] || (ov == best[i] && oi < bidx[i])) { best[i] = ov; bidx[i] = oi; }
        }
    }
    if (tc == 0) {
        #pragma unroll
        for (int i = 0; i < 4; ++i) g_idx[row0 + tr * 4 + i] = bidx[i];
    }
}

// ---------------- gather z_q + commitment-loss partial ----------------
__global__ void k_zq(const float* __restrict__ emb) {
    __shared__ float red[256];
    const size_t N = (size_t)BATCH * DCH * T2;
    float local = 0.f;
    size_t base = (size_t)blockIdx.x * 256 + threadIdx.x;
    for (int k = 0; k < 8; ++k) {
        size_t lin = base + (size_t)k * 524288;
        if (lin < N) {
            int t = (int)(lin & 8191);
            int d = (int)((lin >> 13) & 127);
            int b = (int)(lin >> 20);
            int e = g_idx[b * T2 + t];
            float q  = emb[(size_t)e * DCH + d];
            float zz = g_z[lin];
            g_zq[lin] = q;
            float df = zz - q;
            local += df * df;
        }
    }
    red[threadIdx.x] = local;
    __syncthreads();
    for (int o = 128; o > 0; o >>= 1) {
        if (threadIdx.x < o) red[threadIdx.x] += red[threadIdx.x + o];
        __syncthreads();
    }
    if (threadIdx.x == 0) atomicAdd(&g_acc[1], (double)red[0]);
}

// ---------------- convT1: [B,128,T2] -> gelu -> [B,128,T1], k=8, s=4, p=2 ----------------
__global__ void k_convT1(const float* __restrict__ w, const float* __restrict__ bias) {
    __shared__ float s[128 * 20];
    const int b  = blockIdx.y;
    const int p0 = blockIdx.x * 64;
    const int i0 = p0 / 4 - 1;
    for (int i = threadIdx.x; i < 128 * 18; i += 128) {
        int ci = i / 18, li = i % 18;
        int ii = i0 + li;
        s[ci * 20 + li] = (ii >= 0 && ii < T2) ? g_h[((size_t)(b * DCH + ci)) * T2 + ii] : 0.f;
    }
    __syncthreads();
    const int co = threadIdx.x;
    float acc[64];
    {
        float bv = bias[co];
        #pragma unroll
        for (int t = 0; t < 64; ++t) acc[t] = bv;
    }
    for (int ci = 0; ci < 128; ++ci) {
        const float* wp = w + (ci * 128 + co) * 8;
        const float4 wa = *(const float4*)wp;
        const float4 wb = *(const float4*)(wp + 4);
        const float wv[8] = {wa.x, wa.y, wa.z, wa.w, wb.x, wb.y, wb.z, wb.w};
        const float* row = s + ci * 20;
        #pragma unroll
        for (int li = 0; li < 18; ++li) {
            float v = row[li];
            const int ob = 4 * li - 6;
            #pragma unroll
            for (int k = 0; k < 8; ++k) {
                const int o = ob + k;
                if (o >= 0 && o < 64) acc[o] += wv[k] * v;
            }
        }
    }
    float* outp = g_buf1 + ((size_t)(b * DCH + co)) * T1 + p0;
    #pragma unroll
    for (int t = 0; t < 64; ++t) outp[t] = gelu_exact(acc[t]);
}

// ---------------- convT2 + tanh + write xr + rec-loss partial ----------------
__global__ void k_convT2(const float* __restrict__ w, const float* __restrict__ bias,
                         const float* __restrict__ x, float* __restrict__ out) {
    __shared__ float s[128 * 68];
    __shared__ float sw[1024];
    __shared__ float red[256];
    const int b  = blockIdx.y;
    const int p0 = blockIdx.x * 256;
    const int i0 = p0 / 4 - 1;
    for (int i = threadIdx.x; i < 128 * 66; i += 256) {
        int ci = i / 66, li = i % 66;
        int ii = i0 + li;
        s[ci * 68 + li] = (ii >= 0 && ii < T1) ? g_buf1[((size_t)(b * DCH + ci)) * T1 + ii] : 0.f;
    }
    for (int i = threadIdx.x; i < 1024; i += 256) sw[i] = w[i];
    __syncthreads();
    const int p  = p0 + threadIdx.x;
    const int r  = (p + 2) & 3;
    const int ib = ((p + 2) >> 2) - i0;
    const int ia = ib - 1;
    float acc = bias[0];
    for (int ci = 0; ci < 128; ++ci) {
        acc += sw[ci * 8 + r + 4] * s[ci * 68 + ia] + sw[ci * 8 + r] * s[ci * 68 + ib];
    }
    float xr = tanhf(acc);
    out[XR_OFF + (size_t)b * TLEN + p] = xr;
    float df = xr - x[(size_t)b * TLEN + p];
    red[threadIdx.x] = df * df;
    __syncthreads();
    for (int o = 128; o > 0; o >>= 1) {
        if (threadIdx.x < o) red[threadIdx.x] += red[threadIdx.x + o];
        __syncthreads();
    }
    if (threadIdx.x == 0) atomicAdd(&g_acc[0], (double)red[0]);
}

// ---------------- write idx as float ----------------
__global__ void k_idxout(float* __restrict__ out) {
    int i = blockIdx.x * 256 + threadIdx.x;
    if (i < NROWS) out[IDX_OFF + i] = (float)g_idx[i];
}

// ---------------- finalize scalars: rec, com, ppx ----------------
__global__ void k_final(const float* __restrict__ cs, float* __restrict__ out) {
    __shared__ float red[256];
    __shared__ float s_total;
    float part = 0.f;
    for (int i = threadIdx.x; i < KCODE; i += 256) part += cs[i];
    red[threadIdx.x] = part;
    __syncthreads();
    for (int o = 128; o > 0; o >>= 1) {
        if (threadIdx.x < o) red[threadIdx.x] += red[threadIdx.x + o];
        __syncthreads();
    }
    if (threadIdx.x == 0) s_total = red[0];
    __syncthreads();
    float denom = s_total + 1e-6f;
    float ent = 0.f;
    for (int i = threadIdx.x; i < KCODE; i += 256) {
        float n = cs[i] / denom;
        ent += n * logf(n + 1e-6f);
    }
    red[threadIdx.x] = ent;
    __syncthreads();
    for (int o = 128; o > 0; o >>= 1) {
        if (threadIdx.x < o) red[threadIdx.x] += red[threadIdx.x + o];
        __syncthreads();
    }
    if (threadIdx.x == 0) {
        out[0] = (float)(g_acc[0] / (double)((size_t)BATCH * TLEN));
        out[1] = (float)(g_acc[1] / (double)((size_t)BATCH * DCH * T2));
        out[2] = expf(-red[0]);
    }
}

// ---------------- launch ----------------
extern "C" void kernel_launch(void* const* d_in, const int* in_sizes, int n_in,
                              void* d_out, int out_size) {
    const float* x      = (const float*)d_in[0];
    const float* enc_w1 = (const float*)d_in[1];
    const float* enc_b1 = (const float*)d_in[2];
    const float* enc_w2 = (const float*)d_in[3];
    const float* enc_b2 = (const float*)d_in[4];
    const float* enc_w3 = (const float*)d_in[5];
    const float* enc_b3 = (const float*)d_in[6];
    const float* dec_w0 = (const float*)d_in[7];
    const float* dec_b0 = (const float*)d_in[8];
    const float* dec_wt1= (const float*)d_in[9];
    const float* dec_bt1= (const float*)d_in[10];
    const float* dec_wt2= (const float*)d_in[11];
    const float* dec_bt2= (const float*)d_in[12];
    const float* emb    = (const float*)d_in[13];
    const float* cs     = (const float*)d_in[14];
    float* out = (float*)d_out;

    k_zero<<<1, 32>>>();
    k_conv1<<<dim3(T1 / 256, BATCH), 256>>>(x, enc_w1, enc_b1);
    k_conv2<<<dim3(T2 / 16, BATCH), 128>>>(enc_w2, enc_b2);
    k_conv3<0><<<dim3(T2 / 32, BATCH), 128>>>(enc_w3, enc_b3);
    k_embnorm<<<KCODE / 8, 256>>>(emb);
    k_vqgemm<<<NROWS / 64, 256>>>();
    k_zq<<<2048, 256>>>(emb);
    k_conv3<1><<<dim3(T2 / 32, BATCH), 128>>>(dec_w0, dec_b0);
    k_convT1<<<dim3(T1 / 64, BATCH), 128>>>(dec_wt1, dec_bt1);
    k_convT2<<<dim3(TLEN / 256, BATCH), 256>>>(dec_wt2, dec_bt2, x, out);
    k_idxout<<<NROWS / 256, 256>>>(out);
    k_final<<<1, 256>>>(cs, out);
}

// round 4
// speedup vs baseline: 1.0983x; 1.0983x over previous
#include <cuda_runtime.h>
#include <math.h>

// ---------------- problem constants ----------------
#define BATCH 4
#define TLEN  131072          // waveform length
#define T1    32768           // after conv1 (stride 4)
#define T2    8192            // after conv2 (stride 4)
#define DCH   128             // channels / code dim
#define KCODE 2048            // codebook size
#define NROWS (BATCH*T2)      // 32768 VQ rows

#define XR_OFF  3
#define IDX_OFF (3 + BATCH*TLEN)   // 3 + 524288

// ---------------- scratch (device globals; no cudaMalloc allowed) ----------------
// NOTE: never pass these as kernel arguments from host code (host shadow symbol
// trap on ATS systems) — always reference them directly from device code.
__device__ float g_buf1[BATCH*DCH*T1];   // z1, later reused as decoder upsample-1 output
__device__ float g_z2 [BATCH*DCH*T2];
__device__ float g_z  [BATCH*DCH*T2];    // raw z, d-major (for commitment loss)
__device__ float g_znt[NROWS*DCH];       // normalized z, t-major [row][d]
__device__ float g_zq [BATCH*DCH*T2];
__device__ float g_h  [BATCH*DCH*T2];
__device__ float g_embnT[DCH*KCODE];     // normalized embedding, TRANSPOSED [d][e]
__device__ int   g_idx[NROWS];
__device__ double g_acc[2];              // [0]=rec sum, [1]=com sum

__device__ __forceinline__ float gelu_exact(float v) {
    return 0.5f * v * (1.0f + erff(v * 0.70710678118654752440f));
}

// ---------------- packed f32x2 helpers (Blackwell FFMA2) ----------------
__device__ __forceinline__ unsigned long long f2_fma(unsigned long long a,
                                                     unsigned long long b,
                                                     unsigned long long c) {
    unsigned long long d;
    asm("fma.rn.f32x2 %0, %1, %2, %3;" : "=l"(d) : "l"(a), "l"(b), "l"(c));
    return d;
}
__device__ __forceinline__ unsigned long long f2_dup(float v) {
    unsigned long long d;
    asm("mov.b64 %0, {%1, %1};" : "=l"(d) : "f"(v));
    return d;
}
__device__ __forceinline__ void f2_unpack(unsigned long long p, float& lo, float& hi) {
    asm("mov.b64 {%0, %1}, %2;" : "=f"(lo), "=f"(hi) : "l"(p));
}

// ---------------- zero accumulators ----------------
__global__ void k_zero() {
    if (threadIdx.x < 2) g_acc[threadIdx.x] = 0.0;
}

// ---------------- conv1: [B,1,T] -> gelu -> [B,128,T1], k=8, s=4, p=2 ----------------
__global__ void k_conv1(const float* __restrict__ x, const float* __restrict__ w,
                        const float* __restrict__ bias) {
    __shared__ float sx[1032];
    __shared__ float sw[1024];
    __shared__ float sb[128];
    const int b  = blockIdx.y;
    const int t0 = blockIdx.x * 256;
    const int in0 = 4 * t0 - 2;
    for (int i = threadIdx.x; i < 1032; i += 256) {
        int p = in0 + i;
        sx[i] = (p >= 0 && p < TLEN) ? x[b * TLEN + p] : 0.f;
    }
    for (int i = threadIdx.x; i < 1024; i += 256) sw[i] = w[i];
    if (threadIdx.x < 128) sb[threadIdx.x] = bias[threadIdx.x];
    __syncthreads();
    const int t = threadIdx.x;
    for (int c = 0; c < 128; ++c) {
        float a = sb[c];
        #pragma unroll
        for (int j = 0; j < 8; ++j) a += sw[c * 8 + j] * sx[4 * t + j];
        g_buf1[((size_t)(b * DCH + c)) * T1 + t0 + t] = gelu_exact(a);
    }
}

// ---------------- conv2: [B,128,T1] -> gelu -> [B,128,T2], k=8, s=4, p=2 ----------------
__global__ void k_conv2(const float* __restrict__ w, const float* __restrict__ bias) {
    __shared__ float s[128 * 68];
    const int b  = blockIdx.y;
    const int t0 = blockIdx.x * 16;
    const int in0 = 4 * t0 - 2;
    for (int i = threadIdx.x; i < 128 * 68; i += 128) {
        int ci = i / 68, li = i % 68;
        int p = in0 + li;
        s[i] = (p >= 0 && p < T1) ? g_buf1[((size_t)(b * DCH + ci)) * T1 + p] : 0.f;
    }
    __syncthreads();
    const int c = threadIdx.x;
    float acc[16];
    {
        float bv = bias[c];
        #pragma unroll
        for (int t = 0; t < 16; ++t) acc[t] = bv;
    }
    for (int ci = 0; ci < 128; ++ci) {
        const float* wp = w + (c * 128 + ci) * 8;
        const float4 wa = *(const float4*)wp;
        const float4 wb = *(const float4*)(wp + 4);
        const float4* row = (const float4*)(s + ci * 68);
        float4 v = row[0];
        #pragma unroll
        for (int t = 0; t < 16; ++t) {
            float4 vn = row[t + 1];
            acc[t] += wa.x * v.x + wa.y * v.y + wa.z * v.z + wa.w * v.w
                    + wb.x * vn.x + wb.y * vn.y + wb.z * vn.z + wb.w * vn.w;
            v = vn;
        }
    }
    float* outp = g_z2 + ((size_t)(b * DCH + c)) * T2 + t0;
    #pragma unroll
    for (int t = 0; t < 16; ++t) outp[t] = gelu_exact(acc[t]);
}

// ---------------- k3 conv (s=1, p=1) ----------------
// STAGE 0: enc conv3, g_z2 -> g_z (raw, d-major) + g_znt (L2-normalized, t-major)
// STAGE 1: dec conv0, g_zq -> gelu -> g_h
// Inner loop: 9 vector LDS.128 per channel into registers, sliding in registers.
template <int STAGE>
__global__ void k_conv3(const float* __restrict__ w, const float* __restrict__ bias) {
    const float* __restrict__ in = (STAGE == 0) ? g_z2 : g_zq;
    __shared__ float s[128 * 36];    // span 34, padded; reused for norm reduction
    __shared__ float sinv[32];
    const int b  = blockIdx.y;
    const int t0 = blockIdx.x * 32;
    const int in0 = t0 - 1;
    for (int i = threadIdx.x; i < 128 * 34; i += 128) {
        int ci = i / 34, li = i % 34;
        int p = in0 + li;
        s[ci * 36 + li] = (p >= 0 && p < T2) ? in[((size_t)(b * DCH + ci)) * T2 + p] : 0.f;
    }
    __syncthreads();
    const int c = threadIdx.x;
    float acc[32];
    {
        float bv = bias[c];
        #pragma unroll
        for (int t = 0; t < 32; ++t) acc[t] = bv;
    }
    for (int ci = 0; ci < 128; ++ci) {
        const float* wp = w + (c * 128 + ci) * 3;
        float w0 = wp[0], w1 = wp[1], w2 = wp[2];
        const float4* row4 = (const float4*)(s + ci * 36);
        float f[36];
        #pragma unroll
        for (int q = 0; q < 9; ++q) {
            float4 v = row4[q];
            f[q * 4 + 0] = v.x; f[q * 4 + 1] = v.y; f[q * 4 + 2] = v.z; f[q * 4 + 3] = v.w;
        }
        #pragma unroll
        for (int t = 0; t < 32; ++t)
            acc[t] = fmaf(w0, f[t], fmaf(w1, f[t + 1], fmaf(w2, f[t + 2], acc[t])));
    }
    if (STAGE == 1) {
        float* outp = g_h + ((size_t)(b * DCH + c)) * T2 + t0;
        #pragma unroll
        for (int t = 0; t < 32; ++t) outp[t] = gelu_exact(acc[t]);
        return;
    }
    // STAGE 0: fused row normalization across channels (block owns all 128 c)
    __syncthreads();   // done reading conv input from s
    #pragma unroll
    for (int t = 0; t < 32; ++t) s[t * 132 + c] = acc[t] * acc[t];
    __syncthreads();
    {
        const int t = threadIdx.x >> 2;
        const int q = threadIdx.x & 3;
        float sm = 0.f;
        #pragma unroll
        for (int j = 0; j < 32; ++j) sm += s[t * 132 + q * 32 + j];
        sm += __shfl_xor_sync(0xffffffffu, sm, 1);
        sm += __shfl_xor_sync(0xffffffffu, sm, 2);
        if (q == 0) sinv[t] = 1.0f / fmaxf(sqrtf(sm), 1e-12f);
    }
    __syncthreads();
    {
        float* outp = g_z + ((size_t)(b * DCH + c)) * T2 + t0;
        #pragma unroll
        for (int t = 0; t < 32; ++t) {
            outp[t] = acc[t];
            g_znt[(size_t)(b * T2 + t0 + t) * DCH + c] = acc[t] * sinv[t];
        }
    }
}

// ---------------- normalize embedding rows, store transposed [d][e] ----------------
__global__ void k_embnorm(const float* __restrict__ emb) {
    const int e    = blockIdx.x * 8 + (threadIdx.x >> 5);
    const int lane = threadIdx.x & 31;
    float4 v = *(const float4*)(emb + (size_t)e * DCH + lane * 4);
    float ss = v.x * v.x + v.y * v.y + v.z * v.z + v.w * v.w;
    #pragma unroll
    for (int o = 16; o > 0; o >>= 1) ss += __shfl_xor_sync(0xffffffffu, ss, o);
    float inv = 1.0f / fmaxf(sqrtf(ss), 1e-12f);
    g_embnT[(size_t)(lane * 4 + 0) * KCODE + e] = v.x * inv;
    g_embnT[(size_t)(lane * 4 + 1) * KCODE + e] = v.y * inv;
    g_embnT[(size_t)(lane * 4 + 2) * KCODE + e] = v.z * inv;
    g_embnT[(size_t)(lane * 4 + 3) * KCODE + e] = v.w * inv;
}

// ---------------- VQ GEMM + argmax, packed f32x2 ----------------
// Block: 64 rows x all 2048 codes. 256 threads.
// sA transposed [k][row] so 8 consecutive rows load as 4 natural f32x2 pairs.
// Thread tile: 8 rows x 4 cols. Col tiles of 128 (16 tiles). k chunks of 16.
__global__ __launch_bounds__(256) void k_vqgemm() {
    __shared__ float sA[128 * 64];   // [k][row] 32KB
    __shared__ float sB[16 * 128];   // [kk][c]   8KB
    const int tx   = threadIdx.x;
    const int row0 = blockIdx.x * 64;
    // load + transpose A tile
    for (int it = tx; it < 2048; it += 256) {
        int row = it & 63, kq = it >> 6;
        float4 v = *(const float4*)&g_znt[(size_t)(row0 + row) * DCH + kq * 4];
        sA[(kq * 4 + 0) * 64 + row] = v.x;
        sA[(kq * 4 + 1) * 64 + row] = v.y;
        sA[(kq * 4 + 2) * 64 + row] = v.z;
        sA[(kq * 4 + 3) * 64 + row] = v.w;
    }
    const int tr = tx >> 5;          // warp id: rows tr*8 .. tr*8+7
    const int tc = tx & 31;          // lane: cols tc*4 .. tc*4+3 within tile
    float best[8];
    int   bidx[8];
    #pragma unroll
    for (int i = 0; i < 8; ++i) { best[i] = -1e30f; bidx[i] = 0; }

    for (int ct = 0; ct < KCODE / 128; ++ct) {
        unsigned long long acc[4][4];   // [row-pair][col]
        #pragma unroll
        for (int p = 0; p < 4; ++p)
            #pragma unroll
            for (int j = 0; j < 4; ++j) acc[p][j] = 0ull;
        for (int kc = 0; kc < 8; ++kc) {
            __syncthreads();
            for (int it = tx; it < 512; it += 256) {
                int kk = it >> 5, c4 = it & 31;
                *(float4*)&sB[kk * 128 + c4 * 4] =
                    *(const float4*)&g_embnT[(size_t)(kc * 16 + kk) * KCODE + ct * 128 + c4 * 4];
            }
            __syncthreads();
            #pragma unroll 4
            for (int kk = 0; kk < 16; ++kk) {
                const int k = kc * 16 + kk;
                ulonglong2 aA = *(const ulonglong2*)&sA[k * 64 + tr * 8];
                ulonglong2 aB = *(const ulonglong2*)&sA[k * 64 + tr * 8 + 4];
                float4 bv = *(const float4*)&sB[kk * 128 + tc * 4];
                unsigned long long b0 = f2_dup(bv.x), b1 = f2_dup(bv.y);
                unsigned long long b2 = f2_dup(bv.z), b3 = f2_dup(bv.w);
                acc[0][0] = f2_fma(aA.x, b0, acc[0][0]);
                acc[0][1] = f2_fma(aA.x, b1, acc[0][1]);
                acc[0][2] = f2_fma(aA.x, b2, acc[0][2]);
                acc[0][3] = f2_fma(aA.x, b3, acc[0][3]);
                acc[1][0] = f2_fma(aA.y, b0, acc[1][0]);
                acc[1][1] = f2_fma(aA.y, b1, acc[1][1]);
                acc[1][2] = f2_fma(aA.y, b2, acc[1][2]);
                acc[1][3] = f2_fma(aA.y, b3, acc[1][3]);
                acc[2][0] = f2_fma(aB.x, b0, acc[2][0]);
                acc[2][1] = f2_fma(aB.x, b1, acc[2][1]);
                acc[2][2] = f2_fma(aB.x, b2, acc[2][2]);
                acc[2][3] = f2_fma(aB.x, b3, acc[2][3]);
                acc[3][0] = f2_fma(aB.y, b0, acc[3][0]);
                acc[3][1] = f2_fma(aB.y, b1, acc[3][1]);
                acc[3][2] = f2_fma(aB.y, b2, acc[3][2]);
                acc[3][3] = f2_fma(aB.y, b3, acc[3][3]);
            }
        }
        // epilogue: argmax update (cols ascending; first-max semantics via strict >)
        const int cbase = ct * 128 + tc * 4;
        #pragma unroll
        for (int p = 0; p < 4; ++p) {
            #pragma unroll
            for (int j = 0; j < 4; ++j) {
                float lo, hi;
                f2_unpack(acc[p][j], lo, hi);
                if (lo > best[2 * p + 0]) { best[2 * p + 0] = lo; bidx[2 * p + 0] = cbase + j; }
                if (hi > best[2 * p + 1]) { best[2 * p + 1] = hi; bidx[2 * p + 1] = cbase + j; }
            }
        }
    }
    // reduce across the 32 lanes (cols), first-max tie break on index
    #pragma unroll
    for (int o = 1; o < 32; o <<= 1) {
        #pragma unroll
        for (int i = 0; i < 8; ++i) {
            float ov = __shfl_xor_sync(0xffffffffu, best[i], o);
            int   oi = __shfl_xor_sync(0xffffffffu, bidx[i], o);
            if (ov > best[i] || (ov == best[i] && oi < bidx[i])) { best[i] = ov; bidx[i] = oi; }
        }
    }
    if (tc == 0) {
        #pragma unroll
        for (int i = 0; i < 8; ++i) g_idx[row0 + tr * 8 + i] = bidx[i];
    }
}

// ---------------- gather z_q + commitment-loss partial ----------------
__global__ void k_zq(const float* __restrict__ emb) {
    __shared__ float red[256];
    const size_t N = (size_t)BATCH * DCH * T2;
    float local = 0.f;
    size_t base = (size_t)blockIdx.x * 256 + threadIdx.x;
    for (int k = 0; k < 8; ++k) {
        size_t lin = base + (size_t)k * 524288;
        if (lin < N) {
            int t = (int)(lin & 8191);
            int d = (int)((lin >> 13) & 127);
            int b = (int)(lin >> 20);
            int e = g_idx[b * T2 + t];
            float q  = emb[(size_t)e * DCH + d];
            float zz = g_z[lin];
            g_zq[lin] = q;
            float df = zz - q;
            local += df * df;
        }
    }
    red[threadIdx.x] = local;
    __syncthreads();
    for (int o = 128; o > 0; o >>= 1) {
        if (threadIdx.x < o) red[threadIdx.x] += red[threadIdx.x + o];
        __syncthreads();
    }
    if (threadIdx.x == 0) atomicAdd(&g_acc[1], (double)red[0]);
}

// ---------------- convT1: [B,128,T2] -> gelu -> [B,128,T1], k=8, s=4, p=2 ----------------
__global__ void k_convT1(const float* __restrict__ w, const float* __restrict__ bias) {
    __shared__ float s[128 * 20];
    const int b  = blockIdx.y;
    const int p0 = blockIdx.x * 64;
    const int i0 = p0 / 4 - 1;
    for (int i = threadIdx.x; i < 128 * 18; i += 128) {
        int ci = i / 18, li = i % 18;
        int ii = i0 + li;
        s[ci * 20 + li] = (ii >= 0 && ii < T2) ? g_h[((size_t)(b * DCH + ci)) * T2 + ii] : 0.f;
    }
    __syncthreads();
    const int co = threadIdx.x;
    float acc[64];
    {
        float bv = bias[co];
        #pragma unroll
        for (int t = 0; t < 64; ++t) acc[t] = bv;
    }
    for (int ci = 0; ci < 128; ++ci) {
        const float* wp = w + (ci * 128 + co) * 8;
        const float4 wa = *(const float4*)wp;
        const float4 wb = *(const float4*)(wp + 4);
        const float wv[8] = {wa.x, wa.y, wa.z, wa.w, wb.x, wb.y, wb.z, wb.w};
        const float* row = s + ci * 20;
        #pragma unroll
        for (int li = 0; li < 18; ++li) {
            float v = row[li];
            const int ob = 4 * li - 6;
            #pragma unroll
            for (int k = 0; k < 8; ++k) {
                const int o = ob + k;
                if (o >= 0 && o < 64) acc[o] += wv[k] * v;
            }
        }
    }
    float* outp = g_buf1 + ((size_t)(b * DCH + co)) * T1 + p0;
    #pragma unroll
    for (int t = 0; t < 64; ++t) outp[t] = gelu_exact(acc[t]);
}

// ---------------- convT2 + tanh + write xr + rec-loss partial ----------------
__global__ void k_convT2(const float* __restrict__ w, const float* __restrict__ bias,
                         const float* __restrict__ x, float* __restrict__ out) {
    __shared__ float s[128 * 68];
    __shared__ float sw[1024];
    __shared__ float red[256];
    const int b  = blockIdx.y;
    const int p0 = blockIdx.x * 256;
    const int i0 = p0 / 4 - 1;
    for (int i = threadIdx.x; i < 128 * 66; i += 256) {
        int ci = i / 66, li = i % 66;
        int ii = i0 + li;
        s[ci * 68 + li] = (ii >= 0 && ii < T1) ? g_buf1[((size_t)(b * DCH + ci)) * T1 + ii] : 0.f;
    }
    for (int i = threadIdx.x; i < 1024; i += 256) sw[i] = w[i];
    __syncthreads();
    const int p  = p0 + threadIdx.x;
    const int r  = (p + 2) & 3;
    const int ib = ((p + 2) >> 2) - i0;
    const int ia = ib - 1;
    float acc = bias[0];
    for (int ci = 0; ci < 128; ++ci) {
        acc += sw[ci * 8 + r + 4] * s[ci * 68 + ia] + sw[ci * 8 + r] * s[ci * 68 + ib];
    }
    float xr = tanhf(acc);
    out[XR_OFF + (size_t)b * TLEN + p] = xr;
    float df = xr - x[(size_t)b * TLEN + p];
    red[threadIdx.x] = df * df;
    __syncthreads();
    for (int o = 128; o > 0; o >>= 1) {
        if (threadIdx.x < o) red[threadIdx.x] += red[threadIdx.x + o];
        __syncthreads();
    }
    if (threadIdx.x == 0) atomicAdd(&g_acc[0], (double)red[0]);
}

// ---------------- write idx as float ----------------
__global__ void k_idxout(float* __restrict__ out) {
    int i = blockIdx.x * 256 + threadIdx.x;
    if (i < NROWS) out[IDX_OFF + i] = (float)g_idx[i];
}

// ---------------- finalize scalars: rec, com, ppx ----------------
__global__ void k_final(const float* __restrict__ cs, float* __restrict__ out) {
    __shared__ float red[256];
    __shared__ float s_total;
    float part = 0.f;
    for (int i = threadIdx.x; i < KCODE; i += 256) part += cs[i];
    red[threadIdx.x] = part;
    __syncthreads();
    for (int o = 128; o > 0; o >>= 1) {
        if (threadIdx.x < o) red[threadIdx.x] += red[threadIdx.x + o];
        __syncthreads();
    }
    if (threadIdx.x == 0) s_total = red[0];
    __syncthreads();
    float denom = s_total + 1e-6f;
    float ent = 0.f;
    for (int i = threadIdx.x; i < KCODE; i += 256) {
        float n = cs[i] / denom;
        ent += n * logf(n + 1e-6f);
    }
    red[threadIdx.x] = ent;
    __syncthreads();
    for (int o = 128; o > 0; o >>= 1) {
        if (threadIdx.x < o) red[threadIdx.x] += red[threadIdx.x + o];
        __syncthreads();
    }
    if (threadIdx.x == 0) {
        out[0] = (float)(g_acc[0] / (double)((size_t)BATCH * TLEN));
        out[1] = (float)(g_acc[1] / (double)((size_t)BATCH * DCH * T2));
        out[2] = expf(-red[0]);
    }
}

// ---------------- launch ----------------
extern "C" void kernel_launch(void* const* d_in, const int* in_sizes, int n_in,
                              void* d_out, int out_size) {
    const float* x      = (const float*)d_in[0];
    const float* enc_w1 = (const float*)d_in[1];
    const float* enc_b1 = (const float*)d_in[2];
    const float* enc_w2 = (const float*)d_in[3];
    const float* enc_b2 = (const float*)d_in[4];
    const float* enc_w3 = (const float*)d_in[5];
    const float* enc_b3 = (const float*)d_in[6];
    const float* dec_w0 = (const float*)d_in[7];
    const float* dec_b0 = (const float*)d_in[8];
    const float* dec_wt1= (const float*)d_in[9];
    const float* dec_bt1= (const float*)d_in[10];
    const float* dec_wt2= (const float*)d_in[11];
    const float* dec_bt2= (const float*)d_in[12];
    const float* emb    = (const float*)d_in[13];
    const float* cs     = (const float*)d_in[14];
    float* out = (float*)d_out;

    k_zero<<<1, 32>>>();
    k_conv1<<<dim3(T1 / 256, BATCH), 256>>>(x, enc_w1, enc_b1);
    k_conv2<<<dim3(T2 / 16, BATCH), 128>>>(enc_w2, enc_b2);
    k_conv3<0><<<dim3(T2 / 32, BATCH), 128>>>(enc_w3, enc_b3);
    k_embnorm<<<KCODE / 8, 256>>>(emb);
    k_vqgemm<<<NROWS / 64, 256>>>();
    k_zq<<<2048, 256>>>(emb);
    k_conv3<1><<<dim3(T2 / 32, BATCH), 128>>>(dec_w0, dec_b0);
    k_convT1<<<dim3(T1 / 64, BATCH), 128>>>(dec_wt1, dec_bt1);
    k_convT2<<<dim3(TLEN / 256, BATCH), 256>>>(dec_wt2, dec_bt2, x, out);
    k_idxout<<<NROWS / 256, 256>>>(out);
    k_final<<<1, 256>>>(cs, out);
}